// round 8
// baseline (speedup 1.0000x reference)
#include <cuda_runtime.h>
#include <cstdint>

// GraphPool: 11 segments of N_PER=20000 rows, F=128 floats (512 B/row).
// Segment d: out[row] = max(feat[row], feat[adj_d[rix][0..d-1]])
//
// Bulk-async gather design (FlashMLA sparse-gather pattern): gathered rows
// are fetched with cp.async.bulk (UBLKCP) into shared memory, tracked by an
// mbarrier with complete_tx — this moves the random 512 B reads off the
// per-SM L1tex/LDG miss-tracking path, which five previous configs showed
// caps effective DRAM throughput at ~65%. Self rows stream via LDG; the
// reduction reads gathered rows from smem (cheap LDS.v4).
//
// Block = 256 threads = 8 warps = 8 rows of ONE degree segment
// (deg = blk % 11 interleaves degrees across the wave).

#define N_PER 20000
#define NUM_SEGS 11
#define ROWS_PER_BLOCK 8
#define BLOCKS_PER_SEG (N_PER / ROWS_PER_BLOCK)   // 2500 exactly
#define SMEM_BUF_OFF 1024                          // gather buffers start here

struct AdjPtrs { const int* p[10]; };

__device__ __forceinline__ uint32_t smem_u32(const void* p) {
    uint32_t a;
    asm("{ .reg .u64 t; cvta.to.shared.u64 t, %1; cvt.u32.u64 %0, t; }"
        : "=r"(a) : "l"(p));
    return a;
}

__device__ __forceinline__ bool adj_is_int64(const int* a) {
    return (a[1] | a[3] | a[5] | a[7]) == 0;
}

__device__ __forceinline__ void fmax4(float4& v, const float4& g) {
    v.x = fmaxf(v.x, g.x);
    v.y = fmaxf(v.y, g.y);
    v.z = fmaxf(v.z, g.z);
    v.w = fmaxf(v.w, g.w);
}

__global__ void __launch_bounds__(256)
graphpool_kernel(const char* __restrict__ feat, AdjPtrs adjs,
                 char* __restrict__ out) {
    extern __shared__ char smem[];
    const int tid  = threadIdx.x;
    const int warp = tid >> 5;
    const int lane = tid & 31;
    const int blk  = blockIdx.x;

    const int deg = blk % NUM_SEGS;              // block-uniform degree
    const int sb  = blk / NUM_SEGS;
    const int rix0 = sb * ROWS_PER_BLOCK;        // first row within segment
    const int segbase = deg * N_PER;
    const size_t myrow = (size_t)(segbase + rix0 + warp);

    // ---- deg 0: pure copy, no barrier machinery ----
    if (deg == 0) {
        const float4* src = (const float4*)(feat + myrow * 512);
        float4 v = __ldg(&src[lane]);
        __stcs((float4*)(out + myrow * 512) + lane, v);
        return;
    }

    const int* adj = adjs.p[deg - 1];
    const bool wide = adj_is_int64(adj);
    const int ncopies = ROWS_PER_BLOCK * deg;    // <= 80
    const uint32_t sbase = smem_u32(smem);
    const uint32_t mbar = sbase;                 // mbarrier at offset 0

    if (tid == 0) {
        asm volatile("mbarrier.init.shared.b64 [%0], %1;"
                     :: "r"(mbar), "r"(1) : "memory");
    }
    __syncthreads();

    if (tid == 0) {
        asm volatile("mbarrier.arrive.expect_tx.shared.b64 _, [%0], %1;"
                     :: "r"(mbar), "r"((unsigned)(ncopies * 512)) : "memory");
    }

    // ---- issue bulk gathers: one 512 B row per issuing thread ----
    if (tid < ncopies) {
        const int r = tid / deg;                 // row within block
        const int j = tid - r * deg;             // neighbor slot
        unsigned idx;
        if (wide) {
            idx = (unsigned)__ldg((const long long*)adj +
                                  (size_t)(rix0 + r) * deg + j);
        } else {
            idx = (unsigned)__ldg(adj + (size_t)(rix0 + r) * deg + j);
        }
        const uint32_t dst = sbase + SMEM_BUF_OFF + (unsigned)tid * 512u;
        const char* src = feat + (size_t)idx * 512;
        asm volatile(
            "cp.async.bulk.shared::cluster.global.mbarrier::complete_tx::bytes "
            "[%0], [%1], %2, [%3];"
            :: "r"(dst), "l"(src), "r"(512u), "r"(mbar) : "memory");
    }

    // ---- overlap: self row via LDG while copies are in flight ----
    const float4* selfp = (const float4*)(feat + myrow * 512);
    float4 v = __ldg(&selfp[lane]);

    // ---- wait for all gathers ----
    {
        unsigned done;
        asm volatile(
            "{\n\t.reg .pred p;\n\t"
            "mbarrier.try_wait.parity.acquire.cta.shared::cta.b64 p, [%1], %2;\n\t"
            "selp.b32 %0, 1, 0, p;\n\t}"
            : "=r"(done) : "r"(mbar), "r"(0u) : "memory");
        if (!done) {
            asm volatile(
                "{\n\t.reg .pred P1;\n\t"
                "W%=:\n\t"
                "mbarrier.try_wait.parity.acquire.cta.shared::cta.b64 P1, [%0], %1, 0x989680;\n\t"
                "@P1 bra.uni D%=;\n\t"
                "bra.uni W%=;\n\t"
                "D%=:\n\t}"
                :: "r"(mbar), "r"(0u) : "memory");
        }
    }

    // ---- reduce: warp w consumes its deg gathered rows from smem ----
    const char* buf = smem + SMEM_BUF_OFF + (size_t)warp * deg * 512;
#pragma unroll 5
    for (int j = 0; j < deg; j++) {
        float4 g = *(const float4*)(buf + (size_t)j * 512 + (size_t)lane * 16);
        fmax4(v, g);
    }

    __stcs((float4*)(out + myrow * 512) + lane, v);
}

extern "C" void kernel_launch(void* const* d_in, const int* in_sizes, int n_in,
                              void* d_out, int out_size) {
    // Identify inputs by element count (all distinct):
    //   atom_features: 220000*128 = 28160000
    //   deg_slice:     22 (unused — layout is compile-time known)
    //   adj_d:         20000*d, d = 1..10
    const char* feat = nullptr;
    AdjPtrs adjs;
    for (int d = 0; d < 10; d++) adjs.p[d] = nullptr;

    for (int i = 0; i < n_in; i++) {
        long long sz = in_sizes[i];
        if (sz == (long long)220000 * 128) {
            feat = (const char*)d_in[i];
        } else if (sz >= N_PER && sz <= (long long)N_PER * 10 && sz % N_PER == 0) {
            int d = (int)(sz / N_PER);
            adjs.p[d - 1] = (const int*)d_in[i];
        }
    }

    char* out = (char*)d_out;

    // smem: 1 KB header (mbarrier) + worst-case 8 rows * 10 nbrs * 512 B
    const int smem_bytes = SMEM_BUF_OFF + ROWS_PER_BLOCK * 10 * 512;  // 41984 < 48K

    dim3 grid(NUM_SEGS * BLOCKS_PER_SEG);   // 27500
    dim3 block(256);
    graphpool_kernel<<<grid, block, smem_bytes>>>(feat, adjs, out);
}

// round 9
// speedup vs baseline: 1.5026x; 1.5026x over previous
#include <cuda_runtime.h>
#include <cstdint>

// GraphPool: 11 segments of N_PER=20000 rows, F=128 floats (512 B/row).
// Segment d: out[row] = max(feat[row], feat[adj_d[rix][0..d-1]])
//
// R5 architecture (best known: 87.8us): warp handles 4 rows as two row-pairs;
// within a pair lanes 0-15 -> row A, 16-31 -> row B, 32 B/lane, so one
// 256-bit load serves two rows; up to 2*DEG independent v8 gathers in flight.
// ONLY change vs R5: block->segment map is interleaved (deg = blk % 11) so
// every concurrent wave carries all 11 degrees -> latency-bound low-deg
// blocks overlap with DRAM-hungry high-deg blocks instead of forming
// homogeneous under-utilizing waves.

#define N_PER 20000
#define WARPS_PER_BLOCK 8
#define ROWS_PER_WARP 4
#define ROWS_PER_BLOCK (WARPS_PER_BLOCK * ROWS_PER_WARP)      // 32
#define BLOCKS_PER_SEG (N_PER / ROWS_PER_BLOCK)               // 625 exactly
#define NUM_SEGS 11

struct AdjPtrs { const int* p[10]; };

struct F8 { float4 a, b; };

// 256-bit read-only load, L2 evict-last.
__device__ __forceinline__ F8 ldg_el8(const void* p) {
    F8 r;
    asm volatile("ld.global.nc.L2::evict_last.v8.b32 "
                 "{%0,%1,%2,%3,%4,%5,%6,%7}, [%8];"
                 : "=f"(r.a.x), "=f"(r.a.y), "=f"(r.a.z), "=f"(r.a.w),
                   "=f"(r.b.x), "=f"(r.b.y), "=f"(r.b.z), "=f"(r.b.w)
                 : "l"(p));
    return r;
}

__device__ __forceinline__ void fmax8(F8& v, const F8& g) {
    v.a.x = fmaxf(v.a.x, g.a.x);
    v.a.y = fmaxf(v.a.y, g.a.y);
    v.a.z = fmaxf(v.a.z, g.a.z);
    v.a.w = fmaxf(v.a.w, g.a.w);
    v.b.x = fmaxf(v.b.x, g.b.x);
    v.b.y = fmaxf(v.b.y, g.b.y);
    v.b.z = fmaxf(v.b.z, g.b.z);
    v.b.w = fmaxf(v.b.w, g.b.w);
}

__device__ __forceinline__ bool adj_is_int64(const int* a) {
    return (a[1] | a[3] | a[5] | a[7]) == 0;
}

// One row-PAIR: rows (rix0, rix0+1) of segment `deg`, served by one warp.
// lane 0-15 -> row rix0, lane 16-31 -> row rix0+1.
template <int DEG>
__device__ __forceinline__ void do_pair(const char* __restrict__ feat,
                                        const int* __restrict__ adj,
                                        bool wide,
                                        char* __restrict__ out,
                                        int row0, int rix0,
                                        int lane) {
    const bool hi = (lane & 16) != 0;
    const unsigned sub = (unsigned)(lane & 15) * 32u;          // offset in own row
    const unsigned pairbase = (unsigned)row0 * 512u;

    // Self: rows row0,row0+1 are contiguous -> one v8 load covers both.
    F8 v = ldg_el8(feat + pairbase + (unsigned)lane * 32u);

    if (DEG > 0) {
        unsigned idx[DEG > 0 ? DEG : 1];
        if (wide) {
            const long long* a64 = (const long long*)adj;
#pragma unroll
            for (int j = 0; j < DEG; j++) {
                unsigned iA = (unsigned)__ldg(&a64[(unsigned)rix0 * DEG + j]);
                unsigned iB = (unsigned)__ldg(&a64[(unsigned)(rix0 + 1) * DEG + j]);
                idx[j] = hi ? iB : iA;
            }
        } else {
#pragma unroll
            for (int j = 0; j < DEG; j++) {
                unsigned iA = (unsigned)__ldg(&adj[(unsigned)rix0 * DEG + j]);
                unsigned iB = (unsigned)__ldg(&adj[(unsigned)(rix0 + 1) * DEG + j]);
                idx[j] = hi ? iB : iA;
            }
        }
#pragma unroll
        for (int j = 0; j < DEG; j++) {
            F8 g = ldg_el8(feat + idx[j] * 512u + sub);
            fmax8(v, g);
        }
    }

    // Streaming stores (evict-first): output never re-read.
    char* o = out + pairbase + (unsigned)lane * 32u;
    __stcs((float4*)o, v.a);
    __stcs((float4*)(o + 16), v.b);
}

__global__ void __launch_bounds__(WARPS_PER_BLOCK * 32)
graphpool_kernel(const char* __restrict__ feat, AdjPtrs adjs,
                 char* __restrict__ out) {
    const int warp = threadIdx.x >> 5;
    const int lane = threadIdx.x & 31;
    const int blk  = blockIdx.x;

    // Interleaved map: consecutive blocks cover all 11 degrees ->
    // every concurrent wave mixes latency-bound and DRAM-bound work.
    const int deg       = blk % NUM_SEGS;                     // 0..10
    const int seg_block = blk / NUM_SEGS;                     // 0..624
    const int rix0      = seg_block * ROWS_PER_BLOCK + warp * ROWS_PER_WARP;
    const int row0      = deg * N_PER + rix0;

    const int* adj = (deg > 0) ? adjs.p[deg - 1] : nullptr;
    const bool wide = (deg > 0) ? adj_is_int64(adj) : false;

    switch (deg) {
#define CASE(D) \
        case D: do_pair<D>(feat, adj, wide, out, row0,     rix0,     lane); \
                do_pair<D>(feat, adj, wide, out, row0 + 2, rix0 + 2, lane); \
                break;
        CASE(0) CASE(1) CASE(2) CASE(3) CASE(4) CASE(5)
        CASE(6) CASE(7) CASE(8) CASE(9) CASE(10)
#undef CASE
        default: break;
    }
}

extern "C" void kernel_launch(void* const* d_in, const int* in_sizes, int n_in,
                              void* d_out, int out_size) {
    // Identify inputs by element count (all distinct):
    //   atom_features: 220000*128 = 28160000
    //   deg_slice:     22 (unused — layout is compile-time known)
    //   adj_d:         20000*d, d = 1..10
    const char* feat = nullptr;
    AdjPtrs adjs;
    for (int d = 0; d < 10; d++) adjs.p[d] = nullptr;

    for (int i = 0; i < n_in; i++) {
        long long sz = in_sizes[i];
        if (sz == (long long)220000 * 128) {
            feat = (const char*)d_in[i];
        } else if (sz >= N_PER && sz <= (long long)N_PER * 10 && sz % N_PER == 0) {
            int d = (int)(sz / N_PER);
            adjs.p[d - 1] = (const int*)d_in[i];
        }
    }

    char* out = (char*)d_out;

    dim3 grid(NUM_SEGS * BLOCKS_PER_SEG);   // 6875
    dim3 block(WARPS_PER_BLOCK * 32);       // 256
    graphpool_kernel<<<grid, block>>>(feat, adjs, out);
}

// round 10
// speedup vs baseline: 1.5311x; 1.0189x over previous
#include <cuda_runtime.h>
#include <cstdint>

// GraphPool: 11 segments of N_PER=20000 rows, F=128 floats (512 B/row).
// Segment d: out[row] = max(feat[row], feat[adj_d[rix][0..d-1]])
//
// Warp handles 4 rows (two row-pairs). Within a pair lanes 0-15 -> row A,
// 16-31 -> row B, 32 B/lane: one 256-bit load serves two rows.
// deg 1-4: both pairs processed JOINTLY (2*DEG gathers in flight) since
//   sequential pairs left only DEG outstanding and these segments are
//   latency-bound. deg 5-10: pairs sequential (reg pressure; >=5 in flight).
// launch_bounds(256,5) caps regs at 51 -> 5 CTAs/SM (+25% warps vs R9).
// Interleaved block map (deg = blk % 11) mixes degrees within each wave.

#define N_PER 20000
#define WARPS_PER_BLOCK 8
#define ROWS_PER_WARP 4
#define ROWS_PER_BLOCK (WARPS_PER_BLOCK * ROWS_PER_WARP)      // 32
#define BLOCKS_PER_SEG (N_PER / ROWS_PER_BLOCK)               // 625 exactly
#define NUM_SEGS 11

struct AdjPtrs { const int* p[10]; };
struct F8 { float4 a, b; };

__device__ __forceinline__ F8 ldg_el8(const void* p) {
    F8 r;
    asm volatile("ld.global.nc.L2::evict_last.v8.b32 "
                 "{%0,%1,%2,%3,%4,%5,%6,%7}, [%8];"
                 : "=f"(r.a.x), "=f"(r.a.y), "=f"(r.a.z), "=f"(r.a.w),
                   "=f"(r.b.x), "=f"(r.b.y), "=f"(r.b.z), "=f"(r.b.w)
                 : "l"(p));
    return r;
}

__device__ __forceinline__ void fmax8(F8& v, const F8& g) {
    v.a.x = fmaxf(v.a.x, g.a.x);
    v.a.y = fmaxf(v.a.y, g.a.y);
    v.a.z = fmaxf(v.a.z, g.a.z);
    v.a.w = fmaxf(v.a.w, g.a.w);
    v.b.x = fmaxf(v.b.x, g.b.x);
    v.b.y = fmaxf(v.b.y, g.b.y);
    v.b.z = fmaxf(v.b.z, g.b.z);
    v.b.w = fmaxf(v.b.w, g.b.w);
}

__device__ __forceinline__ bool adj_is_int64(const int* a) {
    return (a[1] | a[3] | a[5] | a[7]) == 0;
}

// Load index j for segment-row r (each half-warp loads only its own row).
template <bool WIDE>
__device__ __forceinline__ unsigned ld_idx(const int* adj, unsigned r, int j, int deg) {
    if (WIDE)
        return (unsigned)__ldg((const long long*)adj + r * deg + j);
    else
        return (unsigned)__ldg(adj + r * deg + j);
}

// Joint processing of BOTH pairs (rows rix0..rix0+3): 2*DEG gathers in flight.
template <int DEG, bool WIDE>
__device__ __forceinline__ void do_joint(const char* __restrict__ feat,
                                         const int* __restrict__ adj,
                                         char* __restrict__ out,
                                         int row0, int rix0, int lane) {
    const unsigned sub  = (unsigned)(lane & 15) * 32u;
    const unsigned loff = (unsigned)lane * 32u;
    const unsigned b0 = (unsigned)row0 * 512u;
    const unsigned b1 = (unsigned)(row0 + 2) * 512u;

    F8 v0 = ldg_el8(feat + b0 + loff);
    F8 v1 = ldg_el8(feat + b1 + loff);

    if (DEG > 0) {
        const unsigned r0 = (unsigned)rix0 + (unsigned)(lane >> 4);  // own half's row
        const unsigned r1 = r0 + 2;
        unsigned idx0[DEG > 0 ? DEG : 1], idx1[DEG > 0 ? DEG : 1];
#pragma unroll
        for (int j = 0; j < DEG; j++) {
            idx0[j] = ld_idx<WIDE>(adj, r0, j, DEG);
            idx1[j] = ld_idx<WIDE>(adj, r1, j, DEG);
        }
#pragma unroll
        for (int j = 0; j < DEG; j++) {
            F8 g0 = ldg_el8(feat + idx0[j] * 512u + sub);
            F8 g1 = ldg_el8(feat + idx1[j] * 512u + sub);
            fmax8(v0, g0);
            fmax8(v1, g1);
        }
    }

    char* o0 = out + b0 + loff;
    __stcs((float4*)o0, v0.a);
    __stcs((float4*)(o0 + 16), v0.b);
    char* o1 = out + b1 + loff;
    __stcs((float4*)o1, v1.a);
    __stcs((float4*)(o1 + 16), v1.b);
}

// Sequential single pair (rows rix0, rix0+1): DEG gathers in flight.
template <int DEG, bool WIDE>
__device__ __forceinline__ void do_pair(const char* __restrict__ feat,
                                        const int* __restrict__ adj,
                                        char* __restrict__ out,
                                        int row0, int rix0, int lane) {
    const unsigned sub  = (unsigned)(lane & 15) * 32u;
    const unsigned loff = (unsigned)lane * 32u;
    const unsigned base = (unsigned)row0 * 512u;

    F8 v = ldg_el8(feat + base + loff);

    const unsigned r = (unsigned)rix0 + (unsigned)(lane >> 4);
    unsigned idx[DEG];
#pragma unroll
    for (int j = 0; j < DEG; j++)
        idx[j] = ld_idx<WIDE>(adj, r, j, DEG);
#pragma unroll
    for (int j = 0; j < DEG; j++) {
        F8 g = ldg_el8(feat + idx[j] * 512u + sub);
        fmax8(v, g);
    }

    char* o = out + base + loff;
    __stcs((float4*)o, v.a);
    __stcs((float4*)(o + 16), v.b);
}

template <bool WIDE>
__device__ __forceinline__ void dispatch(int deg,
                                         const char* __restrict__ feat,
                                         const int* __restrict__ adj,
                                         char* __restrict__ out,
                                         int row0, int rix0, int lane) {
    switch (deg) {
        case 0:  do_joint<0, WIDE>(feat, adj, out, row0, rix0, lane); break;
        case 1:  do_joint<1, WIDE>(feat, adj, out, row0, rix0, lane); break;
        case 2:  do_joint<2, WIDE>(feat, adj, out, row0, rix0, lane); break;
        case 3:  do_joint<3, WIDE>(feat, adj, out, row0, rix0, lane); break;
        case 4:  do_joint<4, WIDE>(feat, adj, out, row0, rix0, lane); break;
#define SEQ(D) \
        case D: do_pair<D, WIDE>(feat, adj, out, row0,     rix0,     lane); \
                do_pair<D, WIDE>(feat, adj, out, row0 + 2, rix0 + 2, lane); \
                break;
        SEQ(5) SEQ(6) SEQ(7) SEQ(8) SEQ(9) SEQ(10)
#undef SEQ
        default: break;
    }
}

__global__ void __launch_bounds__(WARPS_PER_BLOCK * 32, 5)
graphpool_kernel(const char* __restrict__ feat, AdjPtrs adjs,
                 char* __restrict__ out) {
    const int warp = threadIdx.x >> 5;
    const int lane = threadIdx.x & 31;
    const int blk  = blockIdx.x;

    const int deg       = blk % NUM_SEGS;                     // 0..10
    const int seg_block = blk / NUM_SEGS;                     // 0..624
    const int rix0      = seg_block * ROWS_PER_BLOCK + warp * ROWS_PER_WARP;
    const int row0      = deg * N_PER + rix0;

    const int* adj = (deg > 0) ? adjs.p[deg - 1] : nullptr;
    const bool wide = (deg > 0) ? adj_is_int64(adj) : false;

    if (wide) dispatch<true >(deg, feat, adj, out, row0, rix0, lane);
    else      dispatch<false>(deg, feat, adj, out, row0, rix0, lane);
}

extern "C" void kernel_launch(void* const* d_in, const int* in_sizes, int n_in,
                              void* d_out, int out_size) {
    // Identify inputs by element count (all distinct):
    //   atom_features: 220000*128 = 28160000
    //   deg_slice:     22 (unused — layout is compile-time known)
    //   adj_d:         20000*d, d = 1..10
    const char* feat = nullptr;
    AdjPtrs adjs;
    for (int d = 0; d < 10; d++) adjs.p[d] = nullptr;

    for (int i = 0; i < n_in; i++) {
        long long sz = in_sizes[i];
        if (sz == (long long)220000 * 128) {
            feat = (const char*)d_in[i];
        } else if (sz >= N_PER && sz <= (long long)N_PER * 10 && sz % N_PER == 0) {
            int d = (int)(sz / N_PER);
            adjs.p[d - 1] = (const int*)d_in[i];
        }
    }

    char* out = (char*)d_out;

    dim3 grid(NUM_SEGS * BLOCKS_PER_SEG);   // 6875
    dim3 block(WARPS_PER_BLOCK * 32);       // 256
    graphpool_kernel<<<grid, block>>>(feat, adjs, out);
}